// round 13
// baseline (speedup 1.0000x reference)
#include <cuda_runtime.h>
#include <math.h>

#define NN 50000
#define MM 4000
#define EE 320000
#define NTOT 54000   // NN + MM combined counts
#define INV_N (1.f / 50000.f)

// -------- scratch arenas (static __device__; zero-initialized at load) -----
// Invariant: every run leaves all counter/accumulator regions zeroed again.
__device__ float g_farena[48000000];
__device__ int   g_iarena[1200000];

// count degrees + Dn; last block computes W@att vectors (prepatt)
__global__ void k_count_prep(const int* __restrict__ he_n, const int* __restrict__ he_e,
                             const float* __restrict__ he_w,
                             int* ncnt, int* ecnt, float* Dn,
                             const float* __restrict__ h1_w, const float* __restrict__ h1_att,
                             const float* __restrict__ h2_w, const float* __restrict__ h2_att,
                             float* wx1, float* we1, float* wx2, float* we2) {
    if (blockIdx.x == gridDim.x - 1) {
        int k = threadIdx.x;
        if (k >= 128) return;
        for (int h = 0; h < 2; h++) {
            float sx = 0.f, se = 0.f;
            for (int c = 0; c < 128; c++) {
                float w = h1_w[k * 256 + h * 128 + c];
                sx += w * h1_att[h * 256 + c];
                se += w * h1_att[h * 256 + 128 + c];
            }
            wx1[k * 2 + h] = sx;
            we1[k * 2 + h] = se;
        }
        float sx = 0.f, se = 0.f;
        for (int c = 0; c < 128; c++) {
            float w = h2_w[k * 128 + c];
            sx += w * h2_att[c];
            se += w * h2_att[128 + c];
        }
        wx2[k] = sx;
        we2[k] = se;
        return;
    }
    int e = blockIdx.x * blockDim.x + threadIdx.x;
    if (e >= EE) return;
    int n = he_n[e], m = he_e[e];
    atomicAdd(&ncnt[n], 1);
    atomicAdd(&ecnt[m], 1);
    atomicAdd(&Dn[n], he_w[m]);
}

// ---- combined node+edge 3-phase exclusive scan ----------------------------
__global__ void k_scan_red(const int* __restrict__ cnt, int* __restrict__ bsum) {
    __shared__ int sh[256];
    int t = threadIdx.x;
    int i = blockIdx.x * 256 + t;
    sh[t] = (i < NTOT) ? cnt[i] : 0;
    __syncthreads();
    for (int o = 128; o; o >>= 1) {
        if (t < o) sh[t] += sh[t + o];
        __syncthreads();
    }
    if (t == 0) bsum[blockIdx.x] = sh[0];
}
__global__ void k_scan_top(const int* __restrict__ bsum, int* __restrict__ boff,
                           int nb, int* __restrict__ noff, int* __restrict__ eoff) {
    __shared__ int sh[256];
    int t = threadIdx.x;
    int v = (t < nb) ? bsum[t] : 0;
    sh[t] = v;
    __syncthreads();
    for (int o = 1; o < 256; o <<= 1) {
        int u = (t >= o) ? sh[t - o] : 0;
        __syncthreads();
        sh[t] += u;
        __syncthreads();
    }
    if (t < nb) boff[t] = sh[t] - v;
    if (t == 255) { noff[NN] = EE; eoff[MM] = EE; }
}
// also re-zeroes nfill/efill for this run (they are consumed by k_fill next)
__global__ void k_scan_fin(const int* __restrict__ cnt, const int* __restrict__ boff,
                           int* __restrict__ noff, int* __restrict__ eoff,
                           int* __restrict__ nfill, int* __restrict__ efill) {
    __shared__ int sh[256];
    int t = threadIdx.x;
    int i = blockIdx.x * 256 + t;
    int v = (i < NTOT) ? cnt[i] : 0;
    sh[t] = v;
    __syncthreads();
    for (int o = 1; o < 256; o <<= 1) {
        int u = (t >= o) ? sh[t - o] : 0;
        __syncthreads();
        sh[t] += u;
        __syncthreads();
    }
    if (i < NTOT) {
        int val = boff[blockIdx.x] + sh[t] - v;
        if (i < NN) { noff[i] = val; nfill[i] = 0; }
        else        { eoff[i - NN] = val - EE; efill[i - NN] = 0; }
    }
}

// fill CSR; also zeroes ncnt/ecnt (last consumers of counts were the scans)
__global__ void k_fill(const int* __restrict__ he_n, const int* __restrict__ he_e,
                       const int* __restrict__ noff, const int* __restrict__ eoff,
                       int* nfill, int* efill,
                       int* nedge, int* enode, int* eposn,
                       int* ncnt, int* ecnt) {
    int e = blockIdx.x * blockDim.x + threadIdx.x;
    if (e >= EE) return;
    if (e < NN) ncnt[e] = 0;
    if (e < MM) ecnt[e] = 0;
    int n = he_n[e], m = he_e[e];
    int p = atomicAdd(&nfill[n], 1);
    int posn = noff[n] + p;
    nedge[posn] = m;
    int q = atomicAdd(&efill[m], 1);
    enode[eoff[m] + q] = n;
    eposn[eoff[m] + q] = posn;
}

// -------------------- packed f32x2 helpers ---------------------------------
__device__ __forceinline__ void ffma2(unsigned long long& d, unsigned long long a,
                                      unsigned long long b) {
    asm("fma.rn.f32x2 %0, %1, %2, %0;" : "+l"(d) : "l"(a), "l"(b));
}
__device__ __forceinline__ unsigned long long pack2(float x) {
    unsigned long long r;
    asm("mov.b64 %0, {%1, %1};" : "=l"(r) : "f"(x));
    return r;
}
__device__ __forceinline__ float lo32(unsigned long long v) {
    return __uint_as_float((unsigned)v);
}
__device__ __forceinline__ float hi32(unsigned long long v) {
    return __uint_as_float((unsigned)(v >> 32));
}

// last-block BN finalize: st -> aff; then zero st slice + reset ticket
__device__ __forceinline__ void bn_finalize_clear(float* st, const float* g,
                                                  const float* b, float* aff,
                                                  int tid, int* ticket) {
    if (tid < 128) {
        volatile float* vst = st;
        float m = vst[tid] * INV_N;
        float var = vst[128 + tid] * INV_N - m * m;
        float sc = g[tid] * rsqrtf(var + 1e-5f);
        aff[tid] = sc;
        aff[128 + tid] = b[tid] - sc * m;
        vst[tid] = 0.f;
        vst[128 + tid] = 0.f;
    }
    if (tid == 0) *ticket = 0;
}

// ---------------- fused GEMM: C = f(affine(A + y*aplane) @ W [+bias]) [+src]
// 128x128 tile, 256 threads, 8x8 f32x2/thread, 2 blk/SM (R10-proven).
// STATS: fused column stats + last-block BN finalize (ticket).
template <bool AFF, bool BIAS, bool RELU, bool ADDSRC, bool STATS>
__global__ void __launch_bounds__(256, 2) k_gemm2(
    const float* __restrict__ A, const float* __restrict__ aff,
    const float* __restrict__ W, int ldw, int ldc, int aplane,
    const float* __restrict__ bias, const float* __restrict__ src,
    float* __restrict__ C, int rows, float* __restrict__ st,
    const float* __restrict__ bng, const float* __restrict__ bnb,
    float* __restrict__ affo, int* __restrict__ ticket) {
    __shared__ __align__(16) float As[2][16][132];
    __shared__ __align__(16) float Ws[2][16][128];
    __shared__ float ssum[256];

    int tid = threadIdx.x;
    int cg = tid & 15, rg = tid >> 4;
    int ca = cg * 4;
    int cb = ca + 64;
    int rg8 = rg * 8;
    int row_blk = blockIdx.x * 128;
    int col_blk = blockIdx.y * 128;
    int row0 = row_blk + rg8;
    const float* Abase = A + (size_t)blockIdx.y * aplane;

    if (STATS) {
        ssum[tid] = 0.f;
    }

    int ar = tid & 127;
    int ap = (tid >> 7) * 8;
    int arow = row_blk + ar;
    if (arow >= rows) arow = rows - 1;
    const float* aptr = Abase + (size_t)arow * 128 + ap;
    int wk = tid >> 5;
    int wc = (tid & 31) * 4;
    const float* wptr = W + (size_t)wk * ldw + col_blk + wc;

    unsigned long long acc[8][4];
#pragma unroll
    for (int i = 0; i < 8; i++)
#pragma unroll
        for (int j = 0; j < 4; j++) acc[i][j] = 0ull;

    {
        float4 pa0 = *(const float4*)(aptr);
        float4 pa1 = *(const float4*)(aptr + 4);
        float4 pw0 = *(const float4*)(wptr);
        float4 pw1 = *(const float4*)(wptr + 8 * (size_t)ldw);
        if (AFF) {
            float4 s0 = *(const float4*)(aff + ap);
            float4 s1 = *(const float4*)(aff + ap + 4);
            float4 t0 = *(const float4*)(aff + 128 + ap);
            float4 t1 = *(const float4*)(aff + 128 + ap + 4);
            pa0.x = fmaf(pa0.x, s0.x, t0.x); pa0.y = fmaf(pa0.y, s0.y, t0.y);
            pa0.z = fmaf(pa0.z, s0.z, t0.z); pa0.w = fmaf(pa0.w, s0.w, t0.w);
            pa1.x = fmaf(pa1.x, s1.x, t1.x); pa1.y = fmaf(pa1.y, s1.y, t1.y);
            pa1.z = fmaf(pa1.z, s1.z, t1.z); pa1.w = fmaf(pa1.w, s1.w, t1.w);
        }
        As[0][ap + 0][ar] = pa0.x; As[0][ap + 1][ar] = pa0.y;
        As[0][ap + 2][ar] = pa0.z; As[0][ap + 3][ar] = pa0.w;
        As[0][ap + 4][ar] = pa1.x; As[0][ap + 5][ar] = pa1.y;
        As[0][ap + 6][ar] = pa1.z; As[0][ap + 7][ar] = pa1.w;
        *(float4*)&Ws[0][wk][wc]     = pw0;
        *(float4*)&Ws[0][wk + 8][wc] = pw1;
    }

#pragma unroll 1
    for (int kc = 0; kc < 8; kc++) {
        int p = kc & 1;
        __syncthreads();

        float4 pa0, pa1, pw0, pw1;
        if (kc < 7) {
            aptr += 16;
            wptr += 16 * (size_t)ldw;
            pa0 = *(const float4*)(aptr);
            pa1 = *(const float4*)(aptr + 4);
            pw0 = *(const float4*)(wptr);
            pw1 = *(const float4*)(wptr + 8 * (size_t)ldw);
        }

#pragma unroll
        for (int k = 0; k < 16; k++) {
            float4 a0 = *(const float4*)&As[p][k][rg8];
            float4 a1 = *(const float4*)&As[p][k][rg8 + 4];
            ulonglong2 b0 = *(const ulonglong2*)&Ws[p][k][ca];
            ulonglong2 b1 = *(const ulonglong2*)&Ws[p][k][cb];
            float av[8] = {a0.x, a0.y, a0.z, a0.w, a1.x, a1.y, a1.z, a1.w};
#pragma unroll
            for (int i = 0; i < 8; i++) {
                unsigned long long aa = pack2(av[i]);
                ffma2(acc[i][0], aa, b0.x);
                ffma2(acc[i][1], aa, b0.y);
                ffma2(acc[i][2], aa, b1.x);
                ffma2(acc[i][3], aa, b1.y);
            }
        }

        if (kc < 7) {
            int q = p ^ 1;
            if (AFF) {
                int kp = (kc + 1) * 16 + ap;
                float4 s0 = *(const float4*)(aff + kp);
                float4 s1 = *(const float4*)(aff + kp + 4);
                float4 t0 = *(const float4*)(aff + 128 + kp);
                float4 t1 = *(const float4*)(aff + 128 + kp + 4);
                pa0.x = fmaf(pa0.x, s0.x, t0.x); pa0.y = fmaf(pa0.y, s0.y, t0.y);
                pa0.z = fmaf(pa0.z, s0.z, t0.z); pa0.w = fmaf(pa0.w, s0.w, t0.w);
                pa1.x = fmaf(pa1.x, s1.x, t1.x); pa1.y = fmaf(pa1.y, s1.y, t1.y);
                pa1.z = fmaf(pa1.z, s1.z, t1.z); pa1.w = fmaf(pa1.w, s1.w, t1.w);
            }
            As[q][ap + 0][ar] = pa0.x; As[q][ap + 1][ar] = pa0.y;
            As[q][ap + 2][ar] = pa0.z; As[q][ap + 3][ar] = pa0.w;
            As[q][ap + 4][ar] = pa1.x; As[q][ap + 5][ar] = pa1.y;
            As[q][ap + 6][ar] = pa1.z; As[q][ap + 7][ar] = pa1.w;
            *(float4*)&Ws[q][wk][wc]     = pw0;
            *(float4*)&Ws[q][wk + 8][wc] = pw1;
        }
    }

    float csum[8], csq[8];
    if (STATS) {
#pragma unroll
        for (int j = 0; j < 8; j++) csum[j] = csq[j] = 0.f;
    }

#pragma unroll
    for (int i = 0; i < 8; i++) {
        int r = row0 + i;
        bool valid = (r < rows);
        float v[8];
#pragma unroll
        for (int j = 0; j < 2; j++) {
            v[2 * j]     = lo32(acc[i][j]);
            v[2 * j + 1] = hi32(acc[i][j]);
            v[4 + 2 * j]     = lo32(acc[i][2 + j]);
            v[4 + 2 * j + 1] = hi32(acc[i][2 + j]);
        }
#pragma unroll
        for (int j = 0; j < 4; j++) {
            if (BIAS) {
                v[j]     += bias[col_blk + ca + j];
                v[4 + j] += bias[col_blk + cb + j];
            }
            if (RELU) {
                v[j]     = (v[j] >= 0.f)     ? v[j]     : 0.2f * v[j];
                v[4 + j] = (v[4 + j] >= 0.f) ? v[4 + j] : 0.2f * v[4 + j];
            }
        }
        if (ADDSRC && valid) {
            float4 s0 = *(const float4*)(src + (size_t)r * ldc + col_blk + ca);
            float4 s1 = *(const float4*)(src + (size_t)r * ldc + col_blk + cb);
            v[0] += s0.x; v[1] += s0.y; v[2] += s0.z; v[3] += s0.w;
            v[4] += s1.x; v[5] += s1.y; v[6] += s1.z; v[7] += s1.w;
        }
        if (valid) {
            *(float4*)(C + (size_t)r * ldc + col_blk + ca) = make_float4(v[0], v[1], v[2], v[3]);
            *(float4*)(C + (size_t)r * ldc + col_blk + cb) = make_float4(v[4], v[5], v[6], v[7]);
            if (STATS) {
#pragma unroll
                for (int j = 0; j < 8; j++) {
                    csum[j] += v[j];
                    csq[j] = fmaf(v[j], v[j], csq[j]);
                }
            }
        }
    }

    if (STATS) {
        __syncthreads();
#pragma unroll
        for (int j = 0; j < 4; j++) {
            atomicAdd(&ssum[ca + j], csum[j]);
            atomicAdd(&ssum[cb + j], csum[4 + j]);
            atomicAdd(&ssum[128 + ca + j], csq[j]);
            atomicAdd(&ssum[128 + cb + j], csq[4 + j]);
        }
        __syncthreads();
        if (tid < 128) {
            atomicAdd(&st[tid], ssum[tid]);
            atomicAdd(&st[128 + tid], ssum[128 + tid]);
        }
        __threadfence();
        __shared__ int lastblk;
        if (tid == 0)
            lastblk = (atomicAdd(ticket, 1) == (int)(gridDim.x * gridDim.y) - 1);
        __syncthreads();
        if (lastblk) {
            __threadfence();
            bn_finalize_clear(st, bng, bnb, affo, tid, ticket);
        }
    }
}

// an[row,h] = affine(X)·wx[:,h] ; scatter ae[m,h] += affine(X)·we[:,h] over CSR
template <int H>
__global__ void k_rowvec_ae(const float* __restrict__ X, const float* __restrict__ aff,
                            const float* __restrict__ wx, const float* __restrict__ we,
                            const int* __restrict__ noff, const int* __restrict__ nedge,
                            float* __restrict__ an, float* __restrict__ ae, int rows) {
    int row = blockIdx.x * 8 + (threadIdx.x >> 5);
    if (row >= rows) return;
    int lane = threadIdx.x & 31;
    float px[H], pe[H];
#pragma unroll
    for (int h = 0; h < H; h++) px[h] = pe[h] = 0.f;
    for (int k = lane; k < 128; k += 32) {
        float v = fmaf(X[(size_t)row * 128 + k], aff[k], aff[128 + k]);
#pragma unroll
        for (int h = 0; h < H; h++) {
            px[h] = fmaf(v, wx[k * H + h], px[h]);
            pe[h] = fmaf(v, we[k * H + h], pe[h]);
        }
    }
#pragma unroll
    for (int h = 0; h < H; h++) {
        for (int o = 16; o; o >>= 1) {
            px[h] += __shfl_xor_sync(0xffffffffu, px[h], o);
            pe[h] += __shfl_xor_sync(0xffffffffu, pe[h], o);
        }
    }
    if (lane == 0) {
#pragma unroll
        for (int h = 0; h < H; h++) an[(size_t)row * H + h] = px[h];
    }
    int off = noff[row];
    int deg = noff[row + 1] - off;
    for (int i = lane; i < deg; i += 32) {
        int m = nedge[off + i];
#pragma unroll
        for (int h = 0; h < H; h++)
            atomicAdd(&ae[(size_t)m * H + h], pe[h]);
    }
}

// thread-per-node softmax; a stored in node-CSR plane layout a[h*E + pos]
template <int H>
__global__ void k_softmax_t(const float* __restrict__ anode, const float* __restrict__ ae,
                            const int* __restrict__ noff, const int* __restrict__ nedge,
                            float* __restrict__ a, int rows) {
    int n = blockIdx.x * blockDim.x + threadIdx.x;
    if (n >= rows) return;
    int off = noff[n];
    int deg = noff[n + 1] - off;
    if (deg == 0) return;
#pragma unroll
    for (int h = 0; h < H; h++) {
        float an = anode[(size_t)n * H + h];
        float* ap = a + (size_t)h * EE + off;
        float mx = -1e30f;
        for (int i = 0; i < deg; i++) {
            int m = nedge[off + i];
            float l = an + ae[(size_t)m * H + h];
            l = (l >= 0.f) ? l : 0.2f * l;
            ap[i] = l;
            mx = fmaxf(mx, l);
        }
        float s = 0.f;
        for (int i = 0; i < deg; i++) {
            float v = expf(ap[i] - mx);
            ap[i] = v;
            s += v;
        }
        float inv = 1.f / s;
        for (int i = 0; i < deg; i++) ap[i] *= inv;
    }
}

// g[h-plane][m,c] = Binv_m * sum_{e in m} a[e,h] * affine(Z[he_n[e], c])
// also re-zeroes ae[m,:] (its last consumer was softmax, already done)
template <int H>
__global__ void k_gather(const float* __restrict__ Z, const float* __restrict__ aff,
                         const float* __restrict__ a,
                         const int* __restrict__ eoff, const int* __restrict__ enode,
                         const int* __restrict__ eposn, float* __restrict__ g,
                         float* __restrict__ ae) {
    int m = blockIdx.x;
    int c = threadIdx.x;   // 128 threads
    int off = eoff[m];
    int cnt = eoff[m + 1] - off;
    __shared__ int sn[128];
    __shared__ float sa[128 * H];
    float sc = aff[c], sh = aff[128 + c];
    float acc[H];
#pragma unroll
    for (int h = 0; h < H; h++) acc[h] = 0.f;
    for (int base = 0; base < cnt; base += 128) {
        int nb = min(128, cnt - base);
        __syncthreads();
        if (c < nb) {
            int q = off + base + c;
            sn[c] = enode[q];
            int pos = eposn[q];
#pragma unroll
            for (int hh = 0; hh < H; hh++) sa[c * H + hh] = a[(size_t)hh * EE + pos];
        }
        __syncthreads();
        for (int j = 0; j < nb; j++) {
            float v = fmaf(Z[(size_t)sn[j] * 128 + c], sc, sh);
#pragma unroll
            for (int hh = 0; hh < H; hh++) acc[hh] = fmaf(sa[j * H + hh], v, acc[hh]);
        }
    }
    float binv = cnt ? 1.f / (float)cnt : 0.f;
#pragma unroll
    for (int h = 0; h < H; h++)
        g[((size_t)h * MM + m) * 128 + c] = acc[h] * binv;
    if (c < H) ae[(size_t)m * H + c] = 0.f;
}

// U[n,:] = affine(Z[n,:]) + Dinv * mean_h sum_e a[pos,h]*eo[nedge[pos],h,:] + hb
// grid-stride; fused stats + last-block BN finalize for the NEXT layer.
// ZDN: zero Dn after last use (layer-2 instance).
template <int H, bool ZDN>
__global__ void k_out(const float* __restrict__ eo, const float* __restrict__ a,
                      const int* __restrict__ noff, const int* __restrict__ nedge,
                      const float* __restrict__ Z,
                      const float* __restrict__ aff, const float* __restrict__ hb,
                      float* __restrict__ Dn, float* __restrict__ U, int rows,
                      float* __restrict__ st,
                      const float* __restrict__ bng, const float* __restrict__ bnb,
                      float* __restrict__ affo, int* __restrict__ ticket) {
    __shared__ float ssum[256];
    int tid = threadIdx.x;
    int wid = tid >> 5;
    int lane = tid & 31;

    float csum[4], csq[4];
#pragma unroll
    for (int j = 0; j < 4; j++) csum[j] = csq[j] = 0.f;

    for (int n = blockIdx.x * 8 + wid; n < rows; n += gridDim.x * 8) {
        int off = noff[n];
        int deg = noff[n + 1] - off;
        float acc[H][4];
#pragma unroll
        for (int h = 0; h < H; h++)
#pragma unroll
            for (int j = 0; j < 4; j++) acc[h][j] = 0.f;
        for (int i = 0; i < deg; i++) {
            int m = nedge[off + i];
#pragma unroll
            for (int h = 0; h < H; h++) {
                float w = a[(size_t)h * EE + off + i];
#pragma unroll
                for (int j = 0; j < 4; j++)
                    acc[h][j] = fmaf(w, eo[(size_t)m * (128 * H) + h * 128 + lane + 32 * j], acc[h][j]);
            }
        }
        float dn = Dn[n];
        if (ZDN && lane == 0) Dn[n] = 0.f;
        float dinv = (dn > 0.f) ? 1.f / dn : 0.f;
#pragma unroll
        for (int j = 0; j < 4; j++) {
            int c = lane + 32 * j;
            float xb = fmaf(Z[(size_t)n * 128 + c], aff[c], aff[128 + c]);
            float o = (H == 2) ? 0.5f * (acc[0][j] + acc[1][j]) : acc[0][j];
            float v = xb + dinv * o + hb[c];
            U[(size_t)n * 128 + c] = v;
            csum[j] += v;
            csq[j] = fmaf(v, v, csq[j]);
        }
    }

    ssum[tid] = 0.f;
    __syncthreads();
#pragma unroll
    for (int j = 0; j < 4; j++) {
        int c = lane + 32 * j;
        atomicAdd(&ssum[c], csum[j]);
        atomicAdd(&ssum[128 + c], csq[j]);
    }
    __syncthreads();
    if (tid < 128) {
        atomicAdd(&st[tid], ssum[tid]);
        atomicAdd(&st[128 + tid], ssum[128 + tid]);
    }
    __threadfence();
    __shared__ int lastblk;
    if (tid == 0)
        lastblk = (atomicAdd(ticket, 1) == (int)gridDim.x - 1);
    __syncthreads();
    if (lastblk) {
        __threadfence();
        bn_finalize_clear(st, bng, bnb, affo, tid, ticket);
    }
}

// vectorized final affine: out = aff-scale * wbuf + aff-shift
__global__ void k_final(const float4* __restrict__ wb, const float* __restrict__ aff,
                        float4* __restrict__ out, int total4) {
    int i = blockIdx.x * blockDim.x + threadIdx.x;
    if (i < total4) {
        int c = (i * 4) & 127;
        float4 v = wb[i];
        v.x = fmaf(v.x, aff[c],     aff[128 + c]);
        v.y = fmaf(v.y, aff[c + 1], aff[129 + c]);
        v.z = fmaf(v.z, aff[c + 2], aff[130 + c]);
        v.w = fmaf(v.w, aff[c + 3], aff[131 + c]);
        out[i] = v;
    }
}

// ---------------------------------------------------------------------------
extern "C" void kernel_launch(void* const* d_in, const int* in_sizes, int n_in,
                              void* d_out, int out_size) {
    const float* x      = (const float*)d_in[0];
    const int*   he_n   = (const int*)d_in[1];
    const int*   he_e   = (const int*)d_in[2];
    const float* he_w   = (const float*)d_in[3];
    const float* lin1_w = (const float*)d_in[4];
    const float* lin1_b = (const float*)d_in[5];
    const float* bn1_g  = (const float*)d_in[6];
    const float* bn1_b  = (const float*)d_in[7];
    const float* h1_w   = (const float*)d_in[8];
    const float* h1_att = (const float*)d_in[9];
    const float* h1_b   = (const float*)d_in[10];
    const float* bn2_g  = (const float*)d_in[11];
    const float* bn2_b  = (const float*)d_in[12];
    const float* h2_w   = (const float*)d_in[13];
    const float* h2_att = (const float*)d_in[14];
    const float* h2_b   = (const float*)d_in[15];
    const float* bn3_g  = (const float*)d_in[16];
    const float* bn3_b  = (const float*)d_in[17];
    const float* lin2_w = (const float*)d_in[18];
    const float* lin2_b = (const float*)d_in[19];
    const float* bn4_g  = (const float*)d_in[20];
    const float* bn4_b  = (const float*)d_in[21];
    float* out = (float*)d_out;

    float* F = nullptr;
    int*   I = nullptr;
    cudaGetSymbolAddress((void**)&F, g_farena);
    cudaGetSymbolAddress((void**)&I, g_iarena);

    // float arena layout (Dn/st/ae regions rely on the self-zero invariant)
    float* p_Dn   = F;                     // 50000
    float* p_st   = p_Dn + 50000;          // 1024
    float* p_ae1  = p_st + 1024;           // 8000
    float* p_ae2  = p_ae1 + 8000;          // 4000
    float* p_aff  = p_ae2 + 4000;          // 1024
    float* p_wx1  = p_aff + 1024;          // 256
    float* p_we1  = p_wx1 + 256;           // 256
    float* p_wx2  = p_we1 + 256;           // 128
    float* p_we2  = p_wx2 + 128;           // 128
    float* p_z1   = p_we2 + 128;           // 6.4M
    float* p_u1   = p_z1 + 6400000;        // 6.4M
    float* p_u2   = p_u1 + 6400000;        // 6.4M
    float* p_wbuf = p_u2 + 6400000;        // 6.4M
    float* p_g1   = p_wbuf + 6400000;      // 1.024M
    float* p_g2   = p_g1 + 1024000;        // 512000
    float* p_eo1  = p_g2 + 512000;         // 1.024M
    float* p_eo2  = p_eo1 + 1024000;       // 512000
    float* p_a1   = p_eo2 + 512000;        // 640000
    float* p_a2   = p_a1 + 640000;         // 320000
    float* p_an1  = p_a2 + 320000;         // 100000
    float* p_an2  = p_an1 + 100000;        // 50000

    // int arena layout (counts/fills/tickets rely on the self-zero invariant)
    int* p_ncnt  = I;                      // 50000
    int* p_ecnt  = p_ncnt + 50000;         // 4000
    int* p_nfill = p_ecnt + 4000;          // 50000
    int* p_efill = p_nfill + 50000;        // 4000
    int* p_tick  = p_efill + 4000;         // 4
    int* p_noff  = p_tick + 4;             // 50001
    int* p_eoff  = p_noff + 50001;         // 4001
    int* p_nedge = p_eoff + 4001;          // 320000
    int* p_enode = p_nedge + 320000;       // 320000
    int* p_eposn = p_enode + 320000;       // 320000
    int* p_bsum  = p_eposn + 320000;       // 256
    int* p_boff  = p_bsum + 256;           // 256

    const int EB = (EE + 255) / 256;       // 1250
    const int NWB = (NN + 7) / 8;          // 6250
    const int GB2 = (NN + 127) / 128;      // 391
    const int GBM = (MM + 127) / 128;      // 32
    const int TNB = (NN + 255) / 256;      // 196
    const int SCB = (NTOT + 255) / 256;    // 212
    const int OUTB = 592;

    // ---- launches #1-3, then big GEMM at #4 (ncu capture slot) ----
    k_count_prep<<<EB + 1, 256>>>(he_n, he_e, he_w, p_ncnt, p_ecnt, p_Dn,
                                  h1_w, h1_att, h2_w, h2_att,
                                  p_wx1, p_we1, p_wx2, p_we2);
    k_scan_red<<<SCB, 256>>>(p_ncnt, p_bsum);
    k_scan_top<<<1, 256>>>(p_bsum, p_boff, SCB, p_noff, p_eoff);

    // #4: z1 = lrelu(x@lin1+b); stats + BN1 finalize fused
    k_gemm2<false, true, true, false, true><<<dim3(GB2, 1), 256>>>(
        x, nullptr, lin1_w, 128, 128, 0, lin1_b, nullptr, p_z1, NN, p_st,
        bn1_g, bn1_b, p_aff, p_tick + 0);

    k_scan_fin<<<SCB, 256>>>(p_ncnt, p_boff, p_noff, p_eoff, p_nfill, p_efill);
    k_fill<<<EB, 256>>>(he_n, he_e, p_noff, p_eoff, p_nfill, p_efill,
                        p_nedge, p_enode, p_eposn, p_ncnt, p_ecnt);

    // ---- hgconv1 (H=2) ----
    k_rowvec_ae<2><<<NWB, 256>>>(p_z1, p_aff, p_wx1, p_we1, p_noff, p_nedge,
                                 p_an1, p_ae1, NN);
    k_softmax_t<2><<<TNB, 256>>>(p_an1, p_ae1, p_noff, p_nedge, p_a1, NN);
    k_gather<2><<<MM, 128>>>(p_z1, p_aff, p_a1, p_eoff, p_enode, p_eposn, p_g1, p_ae1);
    k_gemm2<false, false, false, false, false><<<dim3(GBM, 2), 256>>>(
        p_g1, nullptr, h1_w, 256, 256, 512000, nullptr, nullptr, p_eo1, MM, nullptr,
        nullptr, nullptr, nullptr, nullptr);
    k_out<2, false><<<OUTB, 256>>>(p_eo1, p_a1, p_noff, p_nedge, p_z1, p_aff, h1_b, p_Dn,
                                   p_u1, NN, p_st + 256, bn2_g, bn2_b, p_aff + 256, p_tick + 1);

    // ---- hgconv2 (H=1) ----
    k_rowvec_ae<1><<<NWB, 256>>>(p_u1, p_aff + 256, p_wx2, p_we2, p_noff, p_nedge,
                                 p_an2, p_ae2, NN);
    k_softmax_t<1><<<TNB, 256>>>(p_an2, p_ae2, p_noff, p_nedge, p_a2, NN);
    k_gather<1><<<MM, 128>>>(p_u1, p_aff + 256, p_a2, p_eoff, p_enode, p_eposn, p_g2, p_ae2);
    k_gemm2<false, false, false, false, false><<<dim3(GBM, 1), 256>>>(
        p_g2, nullptr, h2_w, 128, 128, 0, nullptr, nullptr, p_eo2, MM, nullptr,
        nullptr, nullptr, nullptr, nullptr);
    k_out<1, true><<<OUTB, 256>>>(p_eo2, p_a2, p_noff, p_nedge, p_u1, p_aff + 256, h2_b, p_Dn,
                                  p_u2, NN, p_st + 512, bn3_g, bn3_b, p_aff + 512, p_tick + 2);

    // ---- final: wbuf = x + lrelu(affine3(u2)@lin2+b2); stats + BN4 finalize ----
    k_gemm2<true, true, true, true, true><<<dim3(GB2, 1), 256>>>(
        p_u2, p_aff + 512, lin2_w, 128, 128, 0, lin2_b, x, p_wbuf, NN, p_st + 768,
        bn4_g, bn4_b, p_aff + 768, p_tick + 3);
    k_final<<<(NN * 32 + 255) / 256, 256>>>((const float4*)p_wbuf, p_aff + 768,
                                            (float4*)out, NN * 32);
}

// round 14
// speedup vs baseline: 1.2598x; 1.2598x over previous
#include <cuda_runtime.h>
#include <math.h>

#define NN 50000
#define MM 4000
#define EE 320000
#define NTOT 54000   // NN + MM combined counts
#define INV_N (1.f / 50000.f)

// -------- scratch arenas (static __device__; no allocation allowed) --------
__device__ float g_farena[48000000];
__device__ int   g_iarena[1200000];

// ---------------------------------------------------------------------------
// zero int counters + tickets and float Dn/st/ae regions in one launch
__global__ void k_zero_all(int* ip, int ni, float* fp, int nf) {
    int i = blockIdx.x * blockDim.x + threadIdx.x;
    if (i < ni) ip[i] = 0;
    if (i < nf) fp[i] = 0.f;
}

// count degrees + Dn; last block computes W@att vectors (prepatt)
__global__ void k_count_prep(const int* __restrict__ he_n, const int* __restrict__ he_e,
                             const float* __restrict__ he_w,
                             int* ncnt, int* ecnt, float* Dn,
                             const float* __restrict__ h1_w, const float* __restrict__ h1_att,
                             const float* __restrict__ h2_w, const float* __restrict__ h2_att,
                             float* wx1, float* we1, float* wx2, float* we2) {
    if (blockIdx.x == gridDim.x - 1) {
        int k = threadIdx.x;
        if (k >= 128) return;
        for (int h = 0; h < 2; h++) {
            float sx = 0.f, se = 0.f;
            for (int c = 0; c < 128; c++) {
                float w = h1_w[k * 256 + h * 128 + c];
                sx += w * h1_att[h * 256 + c];
                se += w * h1_att[h * 256 + 128 + c];
            }
            wx1[k * 2 + h] = sx;
            we1[k * 2 + h] = se;
        }
        float sx = 0.f, se = 0.f;
        for (int c = 0; c < 128; c++) {
            float w = h2_w[k * 128 + c];
            sx += w * h2_att[c];
            se += w * h2_att[128 + c];
        }
        wx2[k] = sx;
        we2[k] = se;
        return;
    }
    int e = blockIdx.x * blockDim.x + threadIdx.x;
    if (e >= EE) return;
    int n = he_n[e], m = he_e[e];
    atomicAdd(&ncnt[n], 1);
    atomicAdd(&ecnt[m], 1);
    atomicAdd(&Dn[n], he_w[m]);
}

// ---- combined node+edge 3-phase exclusive scan ----------------------------
__global__ void k_scan_red(const int* __restrict__ cnt, int* __restrict__ bsum) {
    __shared__ int sh[256];
    int t = threadIdx.x;
    int i = blockIdx.x * 256 + t;
    sh[t] = (i < NTOT) ? cnt[i] : 0;
    __syncthreads();
    for (int o = 128; o; o >>= 1) {
        if (t < o) sh[t] += sh[t + o];
        __syncthreads();
    }
    if (t == 0) bsum[blockIdx.x] = sh[0];
}
__global__ void k_scan_top(const int* __restrict__ bsum, int* __restrict__ boff,
                           int nb, int* __restrict__ noff, int* __restrict__ eoff) {
    __shared__ int sh[256];
    int t = threadIdx.x;
    int v = (t < nb) ? bsum[t] : 0;
    sh[t] = v;
    __syncthreads();
    for (int o = 1; o < 256; o <<= 1) {
        int u = (t >= o) ? sh[t - o] : 0;
        __syncthreads();
        sh[t] += u;
        __syncthreads();
    }
    if (t < nb) boff[t] = sh[t] - v;
    if (t == 255) { noff[NN] = EE; eoff[MM] = EE; }
}
__global__ void k_scan_fin(const int* __restrict__ cnt, const int* __restrict__ boff,
                           int* __restrict__ noff, int* __restrict__ eoff) {
    __shared__ int sh[256];
    int t = threadIdx.x;
    int i = blockIdx.x * 256 + t;
    int v = (i < NTOT) ? cnt[i] : 0;
    sh[t] = v;
    __syncthreads();
    for (int o = 1; o < 256; o <<= 1) {
        int u = (t >= o) ? sh[t - o] : 0;
        __syncthreads();
        sh[t] += u;
        __syncthreads();
    }
    if (i < NTOT) {
        int val = boff[blockIdx.x] + sh[t] - v;
        if (i < NN) noff[i] = val;
        else        eoff[i - NN] = val - EE;
    }
}

__global__ void k_fill(const int* __restrict__ he_n, const int* __restrict__ he_e,
                       const int* __restrict__ noff, const int* __restrict__ eoff,
                       int* nfill, int* efill,
                       int* nedge, int* enode, int* eposn) {
    int e = blockIdx.x * blockDim.x + threadIdx.x;
    if (e >= EE) return;
    int n = he_n[e], m = he_e[e];
    int p = atomicAdd(&nfill[n], 1);
    int posn = noff[n] + p;
    nedge[posn] = m;
    int q = atomicAdd(&efill[m], 1);
    enode[eoff[m] + q] = n;
    eposn[eoff[m] + q] = posn;
}

// -------------------- packed f32x2 helpers ---------------------------------
__device__ __forceinline__ void ffma2(unsigned long long& d, unsigned long long a,
                                      unsigned long long b) {
    asm("fma.rn.f32x2 %0, %1, %2, %0;" : "+l"(d) : "l"(a), "l"(b));
}
__device__ __forceinline__ unsigned long long pack2(float x) {
    unsigned long long r;
    asm("mov.b64 %0, {%1, %1};" : "=l"(r) : "f"(x));
    return r;
}
__device__ __forceinline__ float lo32(unsigned long long v) {
    return __uint_as_float((unsigned)v);
}
__device__ __forceinline__ float hi32(unsigned long long v) {
    return __uint_as_float((unsigned)(v >> 32));
}

// last-block BN finalize: st -> aff (scale, shift)
__device__ __forceinline__ void bn_finalize(const float* st, const float* g,
                                            const float* b, float* aff, int tid) {
    if (tid < 128) {
        volatile const float* vst = st;
        float m = vst[tid] * INV_N;
        float var = vst[128 + tid] * INV_N - m * m;
        float sc = g[tid] * rsqrtf(var + 1e-5f);
        aff[tid] = sc;
        aff[128 + tid] = b[tid] - sc * m;
    }
}

// ---------------- fused GEMM: C = f(affine(A + y*aplane) @ W [+bias]) [+src]
// 128x128 tile (R10-proven config), 256 threads, 8x8 f32x2/thread, 2 blk/SM.
// STATS: fused column stats + last-block BN finalize (ticket).
template <bool AFF, bool BIAS, bool RELU, bool ADDSRC, bool STATS>
__global__ void __launch_bounds__(256, 2) k_gemm2(
    const float* __restrict__ A, const float* __restrict__ aff,
    const float* __restrict__ W, int ldw, int ldc, int aplane,
    const float* __restrict__ bias, const float* __restrict__ src,
    float* __restrict__ C, int rows, float* __restrict__ st,
    const float* __restrict__ bng, const float* __restrict__ bnb,
    float* __restrict__ affo, int* __restrict__ ticket) {
    __shared__ __align__(16) float As[2][16][132];
    __shared__ __align__(16) float Ws[2][16][128];
    __shared__ float ssum[256];

    int tid = threadIdx.x;
    int cg = tid & 15, rg = tid >> 4;
    int ca = cg * 4;
    int cb = ca + 64;
    int rg8 = rg * 8;
    int row_blk = blockIdx.x * 128;
    int col_blk = blockIdx.y * 128;
    int row0 = row_blk + rg8;
    const float* Abase = A + (size_t)blockIdx.y * aplane;

    if (STATS) {
        ssum[tid] = 0.f;
    }

    int ar = tid & 127;
    int ap = (tid >> 7) * 8;
    int arow = row_blk + ar;
    if (arow >= rows) arow = rows - 1;
    const float* aptr = Abase + (size_t)arow * 128 + ap;
    int wk = tid >> 5;
    int wc = (tid & 31) * 4;
    const float* wptr = W + (size_t)wk * ldw + col_blk + wc;

    unsigned long long acc[8][4];
#pragma unroll
    for (int i = 0; i < 8; i++)
#pragma unroll
        for (int j = 0; j < 4; j++) acc[i][j] = 0ull;

    {
        float4 pa0 = *(const float4*)(aptr);
        float4 pa1 = *(const float4*)(aptr + 4);
        float4 pw0 = *(const float4*)(wptr);
        float4 pw1 = *(const float4*)(wptr + 8 * (size_t)ldw);
        if (AFF) {
            float4 s0 = *(const float4*)(aff + ap);
            float4 s1 = *(const float4*)(aff + ap + 4);
            float4 t0 = *(const float4*)(aff + 128 + ap);
            float4 t1 = *(const float4*)(aff + 128 + ap + 4);
            pa0.x = fmaf(pa0.x, s0.x, t0.x); pa0.y = fmaf(pa0.y, s0.y, t0.y);
            pa0.z = fmaf(pa0.z, s0.z, t0.z); pa0.w = fmaf(pa0.w, s0.w, t0.w);
            pa1.x = fmaf(pa1.x, s1.x, t1.x); pa1.y = fmaf(pa1.y, s1.y, t1.y);
            pa1.z = fmaf(pa1.z, s1.z, t1.z); pa1.w = fmaf(pa1.w, s1.w, t1.w);
        }
        As[0][ap + 0][ar] = pa0.x; As[0][ap + 1][ar] = pa0.y;
        As[0][ap + 2][ar] = pa0.z; As[0][ap + 3][ar] = pa0.w;
        As[0][ap + 4][ar] = pa1.x; As[0][ap + 5][ar] = pa1.y;
        As[0][ap + 6][ar] = pa1.z; As[0][ap + 7][ar] = pa1.w;
        *(float4*)&Ws[0][wk][wc]     = pw0;
        *(float4*)&Ws[0][wk + 8][wc] = pw1;
    }

#pragma unroll 1
    for (int kc = 0; kc < 8; kc++) {
        int p = kc & 1;
        __syncthreads();

        float4 pa0, pa1, pw0, pw1;
        if (kc < 7) {
            aptr += 16;
            wptr += 16 * (size_t)ldw;
            pa0 = *(const float4*)(aptr);
            pa1 = *(const float4*)(aptr + 4);
            pw0 = *(const float4*)(wptr);
            pw1 = *(const float4*)(wptr + 8 * (size_t)ldw);
        }

#pragma unroll
        for (int k = 0; k < 16; k++) {
            float4 a0 = *(const float4*)&As[p][k][rg8];
            float4 a1 = *(const float4*)&As[p][k][rg8 + 4];
            ulonglong2 b0 = *(const ulonglong2*)&Ws[p][k][ca];
            ulonglong2 b1 = *(const ulonglong2*)&Ws[p][k][cb];
            float av[8] = {a0.x, a0.y, a0.z, a0.w, a1.x, a1.y, a1.z, a1.w};
#pragma unroll
            for (int i = 0; i < 8; i++) {
                unsigned long long aa = pack2(av[i]);
                ffma2(acc[i][0], aa, b0.x);
                ffma2(acc[i][1], aa, b0.y);
                ffma2(acc[i][2], aa, b1.x);
                ffma2(acc[i][3], aa, b1.y);
            }
        }

        if (kc < 7) {
            int q = p ^ 1;
            if (AFF) {
                int kp = (kc + 1) * 16 + ap;
                float4 s0 = *(const float4*)(aff + kp);
                float4 s1 = *(const float4*)(aff + kp + 4);
                float4 t0 = *(const float4*)(aff + 128 + kp);
                float4 t1 = *(const float4*)(aff + 128 + kp + 4);
                pa0.x = fmaf(pa0.x, s0.x, t0.x); pa0.y = fmaf(pa0.y, s0.y, t0.y);
                pa0.z = fmaf(pa0.z, s0.z, t0.z); pa0.w = fmaf(pa0.w, s0.w, t0.w);
                pa1.x = fmaf(pa1.x, s1.x, t1.x); pa1.y = fmaf(pa1.y, s1.y, t1.y);
                pa1.z = fmaf(pa1.z, s1.z, t1.z); pa1.w = fmaf(pa1.w, s1.w, t1.w);
            }
            As[q][ap + 0][ar] = pa0.x; As[q][ap + 1][ar] = pa0.y;
            As[q][ap + 2][ar] = pa0.z; As[q][ap + 3][ar] = pa0.w;
            As[q][ap + 4][ar] = pa1.x; As[q][ap + 5][ar] = pa1.y;
            As[q][ap + 6][ar] = pa1.z; As[q][ap + 7][ar] = pa1.w;
            *(float4*)&Ws[q][wk][wc]     = pw0;
            *(float4*)&Ws[q][wk + 8][wc] = pw1;
        }
    }

    float csum[8], csq[8];
    if (STATS) {
#pragma unroll
        for (int j = 0; j < 8; j++) csum[j] = csq[j] = 0.f;
    }

#pragma unroll
    for (int i = 0; i < 8; i++) {
        int r = row0 + i;
        bool valid = (r < rows);
        float v[8];
#pragma unroll
        for (int j = 0; j < 2; j++) {
            v[2 * j]     = lo32(acc[i][j]);
            v[2 * j + 1] = hi32(acc[i][j]);
            v[4 + 2 * j]     = lo32(acc[i][2 + j]);
            v[4 + 2 * j + 1] = hi32(acc[i][2 + j]);
        }
#pragma unroll
        for (int j = 0; j < 4; j++) {
            if (BIAS) {
                v[j]     += bias[col_blk + ca + j];
                v[4 + j] += bias[col_blk + cb + j];
            }
            if (RELU) {
                v[j]     = (v[j] >= 0.f)     ? v[j]     : 0.2f * v[j];
                v[4 + j] = (v[4 + j] >= 0.f) ? v[4 + j] : 0.2f * v[4 + j];
            }
        }
        if (ADDSRC && valid) {
            float4 s0 = *(const float4*)(src + (size_t)r * ldc + col_blk + ca);
            float4 s1 = *(const float4*)(src + (size_t)r * ldc + col_blk + cb);
            v[0] += s0.x; v[1] += s0.y; v[2] += s0.z; v[3] += s0.w;
            v[4] += s1.x; v[5] += s1.y; v[6] += s1.z; v[7] += s1.w;
        }
        if (valid) {
            *(float4*)(C + (size_t)r * ldc + col_blk + ca) = make_float4(v[0], v[1], v[2], v[3]);
            *(float4*)(C + (size_t)r * ldc + col_blk + cb) = make_float4(v[4], v[5], v[6], v[7]);
            if (STATS) {
#pragma unroll
                for (int j = 0; j < 8; j++) {
                    csum[j] += v[j];
                    csq[j] = fmaf(v[j], v[j], csq[j]);
                }
            }
        }
    }

    if (STATS) {
        __syncthreads();
#pragma unroll
        for (int j = 0; j < 4; j++) {
            atomicAdd(&ssum[ca + j], csum[j]);
            atomicAdd(&ssum[cb + j], csum[4 + j]);
            atomicAdd(&ssum[128 + ca + j], csq[j]);
            atomicAdd(&ssum[128 + cb + j], csq[4 + j]);
        }
        __syncthreads();
        if (tid < 128) {
            atomicAdd(&st[tid], ssum[tid]);
            atomicAdd(&st[128 + tid], ssum[128 + tid]);
        }
        __threadfence();
        __shared__ int lastblk;
        if (tid == 0)
            lastblk = (atomicAdd(ticket, 1) == (int)(gridDim.x * gridDim.y) - 1);
        __syncthreads();
        if (lastblk) {
            __threadfence();
            bn_finalize(st, bng, bnb, affo, tid);
        }
    }
}

// an[row,h] = affine(X)·wx[:,h] ; scatter ae[m,h] += affine(X)·we[:,h] over CSR
template <int H>
__global__ void k_rowvec_ae(const float* __restrict__ X, const float* __restrict__ aff,
                            const float* __restrict__ wx, const float* __restrict__ we,
                            const int* __restrict__ noff, const int* __restrict__ nedge,
                            float* __restrict__ an, float* __restrict__ ae, int rows) {
    int row = blockIdx.x * 8 + (threadIdx.x >> 5);
    if (row >= rows) return;
    int lane = threadIdx.x & 31;
    float px[H], pe[H];
#pragma unroll
    for (int h = 0; h < H; h++) px[h] = pe[h] = 0.f;
    for (int k = lane; k < 128; k += 32) {
        float v = fmaf(X[(size_t)row * 128 + k], aff[k], aff[128 + k]);
#pragma unroll
        for (int h = 0; h < H; h++) {
            px[h] = fmaf(v, wx[k * H + h], px[h]);
            pe[h] = fmaf(v, we[k * H + h], pe[h]);
        }
    }
#pragma unroll
    for (int h = 0; h < H; h++) {
        for (int o = 16; o; o >>= 1) {
            px[h] += __shfl_xor_sync(0xffffffffu, px[h], o);
            pe[h] += __shfl_xor_sync(0xffffffffu, pe[h], o);
        }
    }
    if (lane == 0) {
#pragma unroll
        for (int h = 0; h < H; h++) an[(size_t)row * H + h] = px[h];
    }
    int off = noff[row];
    int deg = noff[row + 1] - off;
    for (int i = lane; i < deg; i += 32) {
        int m = nedge[off + i];
#pragma unroll
        for (int h = 0; h < H; h++)
            atomicAdd(&ae[(size_t)m * H + h], pe[h]);
    }
}

// thread-per-node softmax; a stored in node-CSR plane layout a[h*E + pos]
template <int H>
__global__ void k_softmax_t(const float* __restrict__ anode, const float* __restrict__ ae,
                            const int* __restrict__ noff, const int* __restrict__ nedge,
                            float* __restrict__ a, int rows) {
    int n = blockIdx.x * blockDim.x + threadIdx.x;
    if (n >= rows) return;
    int off = noff[n];
    int deg = noff[n + 1] - off;
    if (deg == 0) return;
#pragma unroll
    for (int h = 0; h < H; h++) {
        float an = anode[(size_t)n * H + h];
        float* ap = a + (size_t)h * EE + off;
        float mx = -1e30f;
        for (int i = 0; i < deg; i++) {
            int m = nedge[off + i];
            float l = an + ae[(size_t)m * H + h];
            l = (l >= 0.f) ? l : 0.2f * l;
            ap[i] = l;
            mx = fmaxf(mx, l);
        }
        float s = 0.f;
        for (int i = 0; i < deg; i++) {
            float v = expf(ap[i] - mx);
            ap[i] = v;
            s += v;
        }
        float inv = 1.f / s;
        for (int i = 0; i < deg; i++) ap[i] *= inv;
    }
}

// g[h-plane][m,c] = Binv_m * sum_{e in m} a[e,h] * affine(Z[he_n[e], c])
template <int H>
__global__ void k_gather(const float* __restrict__ Z, const float* __restrict__ aff,
                         const float* __restrict__ a,
                         const int* __restrict__ eoff, const int* __restrict__ enode,
                         const int* __restrict__ eposn, float* __restrict__ g) {
    int m = blockIdx.x;
    int c = threadIdx.x;   // 128 threads
    int off = eoff[m];
    int cnt = eoff[m + 1] - off;
    __shared__ int sn[128];
    __shared__ float sa[128 * H];
    float sc = aff[c], sh = aff[128 + c];
    float acc[H];
#pragma unroll
    for (int h = 0; h < H; h++) acc[h] = 0.f;
    for (int base = 0; base < cnt; base += 128) {
        int nb = min(128, cnt - base);
        __syncthreads();
        if (c < nb) {
            int q = off + base + c;
            sn[c] = enode[q];
            int pos = eposn[q];
#pragma unroll
            for (int hh = 0; hh < H; hh++) sa[c * H + hh] = a[(size_t)hh * EE + pos];
        }
        __syncthreads();
        for (int j = 0; j < nb; j++) {
            float v = fmaf(Z[(size_t)sn[j] * 128 + c], sc, sh);
#pragma unroll
            for (int hh = 0; hh < H; hh++) acc[hh] = fmaf(sa[j * H + hh], v, acc[hh]);
        }
    }
    float binv = cnt ? 1.f / (float)cnt : 0.f;
#pragma unroll
    for (int h = 0; h < H; h++)
        g[((size_t)h * MM + m) * 128 + c] = acc[h] * binv;
}

// U[n,:] = affine(Z[n,:]) + Dinv * mean_h sum_e a[pos,h]*eo[nedge[pos],h,:] + hb
// grid-stride; fused stats + last-block BN finalize for the NEXT layer
template <int H>
__global__ void k_out(const float* __restrict__ eo, const float* __restrict__ a,
                      const int* __restrict__ noff, const int* __restrict__ nedge,
                      const float* __restrict__ Z,
                      const float* __restrict__ aff, const float* __restrict__ hb,
                      const float* __restrict__ Dn, float* __restrict__ U, int rows,
                      float* __restrict__ st,
                      const float* __restrict__ bng, const float* __restrict__ bnb,
                      float* __restrict__ affo, int* __restrict__ ticket) {
    __shared__ float ssum[256];
    int tid = threadIdx.x;
    int wid = tid >> 5;
    int lane = tid & 31;

    float csum[4], csq[4];
#pragma unroll
    for (int j = 0; j < 4; j++) csum[j] = csq[j] = 0.f;

    for (int n = blockIdx.x * 8 + wid; n < rows; n += gridDim.x * 8) {
        int off = noff[n];
        int deg = noff[n + 1] - off;
        float acc[H][4];
#pragma unroll
        for (int h = 0; h < H; h++)
#pragma unroll
            for (int j = 0; j < 4; j++) acc[h][j] = 0.f;
        for (int i = 0; i < deg; i++) {
            int m = nedge[off + i];
#pragma unroll
            for (int h = 0; h < H; h++) {
                float w = a[(size_t)h * EE + off + i];
#pragma unroll
                for (int j = 0; j < 4; j++)
                    acc[h][j] = fmaf(w, eo[(size_t)m * (128 * H) + h * 128 + lane + 32 * j], acc[h][j]);
            }
        }
        float dn = Dn[n];
        float dinv = (dn > 0.f) ? 1.f / dn : 0.f;
#pragma unroll
        for (int j = 0; j < 4; j++) {
            int c = lane + 32 * j;
            float xb = fmaf(Z[(size_t)n * 128 + c], aff[c], aff[128 + c]);
            float o = (H == 2) ? 0.5f * (acc[0][j] + acc[1][j]) : acc[0][j];
            float v = xb + dinv * o + hb[c];
            U[(size_t)n * 128 + c] = v;
            csum[j] += v;
            csq[j] = fmaf(v, v, csq[j]);
        }
    }

    ssum[tid] = 0.f;
    __syncthreads();
#pragma unroll
    for (int j = 0; j < 4; j++) {
        int c = lane + 32 * j;
        atomicAdd(&ssum[c], csum[j]);
        atomicAdd(&ssum[128 + c], csq[j]);
    }
    __syncthreads();
    if (tid < 128) {
        atomicAdd(&st[tid], ssum[tid]);
        atomicAdd(&st[128 + tid], ssum[128 + tid]);
    }
    __threadfence();
    __shared__ int lastblk;
    if (tid == 0)
        lastblk = (atomicAdd(ticket, 1) == (int)gridDim.x - 1);
    __syncthreads();
    if (lastblk) {
        __threadfence();
        bn_finalize(st, bng, bnb, affo, tid);
    }
}

// vectorized final affine: out = aff-scale * wbuf + aff-shift
__global__ void k_final(const float4* __restrict__ wb, const float* __restrict__ aff,
                        float4* __restrict__ out, int total4) {
    int i = blockIdx.x * blockDim.x + threadIdx.x;
    if (i < total4) {
        int c = (i * 4) & 127;
        float4 v = wb[i];
        v.x = fmaf(v.x, aff[c],     aff[128 + c]);
        v.y = fmaf(v.y, aff[c + 1], aff[129 + c]);
        v.z = fmaf(v.z, aff[c + 2], aff[130 + c]);
        v.w = fmaf(v.w, aff[c + 3], aff[131 + c]);
        out[i] = v;
    }
}

// ---------------------------------------------------------------------------
extern "C" void kernel_launch(void* const* d_in, const int* in_sizes, int n_in,
                              void* d_out, int out_size) {
    const float* x      = (const float*)d_in[0];
    const int*   he_n   = (const int*)d_in[1];
    const int*   he_e   = (const int*)d_in[2];
    const float* he_w   = (const float*)d_in[3];
    const float* lin1_w = (const float*)d_in[4];
    const float* lin1_b = (const float*)d_in[5];
    const float* bn1_g  = (const float*)d_in[6];
    const float* bn1_b  = (const float*)d_in[7];
    const float* h1_w   = (const float*)d_in[8];
    const float* h1_att = (const float*)d_in[9];
    const float* h1_b   = (const float*)d_in[10];
    const float* bn2_g  = (const float*)d_in[11];
    const float* bn2_b  = (const float*)d_in[12];
    const float* h2_w   = (const float*)d_in[13];
    const float* h2_att = (const float*)d_in[14];
    const float* h2_b   = (const float*)d_in[15];
    const float* bn3_g  = (const float*)d_in[16];
    const float* bn3_b  = (const float*)d_in[17];
    const float* lin2_w = (const float*)d_in[18];
    const float* lin2_b = (const float*)d_in[19];
    const float* bn4_g  = (const float*)d_in[20];
    const float* bn4_b  = (const float*)d_in[21];
    float* out = (float*)d_out;

    float* F = nullptr;
    int*   I = nullptr;
    cudaGetSymbolAddress((void**)&F, g_farena);
    cudaGetSymbolAddress((void**)&I, g_iarena);

    // float arena layout (zero prefix: Dn + st + ae1 + ae2 = 63024)
    float* p_Dn   = F;                     // 50000
    float* p_st   = p_Dn + 50000;          // 1024
    float* p_ae1  = p_st + 1024;           // 8000
    float* p_ae2  = p_ae1 + 8000;          // 4000
    float* p_aff  = p_ae2 + 4000;          // 1024
    float* p_wx1  = p_aff + 1024;          // 256
    float* p_we1  = p_wx1 + 256;           // 256
    float* p_wx2  = p_we1 + 256;           // 128
    float* p_we2  = p_wx2 + 128;           // 128
    float* p_z1   = p_we2 + 128;           // 6.4M
    float* p_u1   = p_z1 + 6400000;        // 6.4M
    float* p_u2   = p_u1 + 6400000;        // 6.4M
    float* p_wbuf = p_u2 + 6400000;        // 6.4M
    float* p_g1   = p_wbuf + 6400000;      // 1.024M
    float* p_g2   = p_g1 + 1024000;        // 512000
    float* p_eo1  = p_g2 + 512000;         // 1.024M
    float* p_eo2  = p_eo1 + 1024000;       // 512000
    float* p_a1   = p_eo2 + 512000;        // 640000
    float* p_a2   = p_a1 + 640000;         // 320000
    float* p_an1  = p_a2 + 320000;         // 100000
    float* p_an2  = p_an1 + 100000;        // 50000

    // int arena layout (zero prefix: counts + fills + tickets = 108004)
    int* p_ncnt  = I;                      // 50000
    int* p_ecnt  = p_ncnt + 50000;         // 4000
    int* p_nfill = p_ecnt + 4000;          // 50000
    int* p_efill = p_nfill + 50000;        // 4000
    int* p_tick  = p_efill + 4000;         // 4
    int* p_noff  = p_tick + 4;             // 50001
    int* p_eoff  = p_noff + 50001;         // 4001
    int* p_nedge = p_eoff + 4001;          // 320000
    int* p_enode = p_nedge + 320000;       // 320000
    int* p_eposn = p_enode + 320000;       // 320000
    int* p_bsum  = p_eposn + 320000;       // 256
    int* p_boff  = p_bsum + 256;           // 256

    const int EB = (EE + 255) / 256;       // 1250
    const int NWB = (NN + 7) / 8;          // 6250
    const int GB2 = (NN + 127) / 128;      // 391
    const int GBM = (MM + 127) / 128;      // 32
    const int TNB = (NN + 255) / 256;      // 196
    const int SCB = (NTOT + 255) / 256;    // 212
    const int OUTB = 592;

    // ---- launches #1-3, then big GEMM at #4 (ncu capture slot) ----
    k_zero_all<<<(108004 + 255) / 256, 256>>>(I, 108004, F, 63024);
    k_count_prep<<<EB + 1, 256>>>(he_n, he_e, he_w, p_ncnt, p_ecnt, p_Dn,
                                  h1_w, h1_att, h2_w, h2_att,
                                  p_wx1, p_we1, p_wx2, p_we2);
    k_scan_red<<<SCB, 256>>>(p_ncnt, p_bsum);

    // #4: z1 = lrelu(x@lin1+b); stats + BN1 finalize fused
    k_gemm2<false, true, true, false, true><<<dim3(GB2, 1), 256>>>(
        x, nullptr, lin1_w, 128, 128, 0, lin1_b, nullptr, p_z1, NN, p_st,
        bn1_g, bn1_b, p_aff, p_tick + 0);

    k_scan_top<<<1, 256>>>(p_bsum, p_boff, SCB, p_noff, p_eoff);
    k_scan_fin<<<SCB, 256>>>(p_ncnt, p_boff, p_noff, p_eoff);
    k_fill<<<EB, 256>>>(he_n, he_e, p_noff, p_eoff, p_nfill, p_efill,
                        p_nedge, p_enode, p_eposn);

    // ---- hgconv1 (H=2) ----
    k_rowvec_ae<2><<<NWB, 256>>>(p_z1, p_aff, p_wx1, p_we1, p_noff, p_nedge,
                                 p_an1, p_ae1, NN);
    k_softmax_t<2><<<TNB, 256>>>(p_an1, p_ae1, p_noff, p_nedge, p_a1, NN);
    k_gather<2><<<MM, 128>>>(p_z1, p_aff, p_a1, p_eoff, p_enode, p_eposn, p_g1);
    k_gemm2<false, false, false, false, false><<<dim3(GBM, 2), 256>>>(
        p_g1, nullptr, h1_w, 256, 256, 512000, nullptr, nullptr, p_eo1, MM, nullptr,
        nullptr, nullptr, nullptr, nullptr);
    k_out<2><<<OUTB, 256>>>(p_eo1, p_a1, p_noff, p_nedge, p_z1, p_aff, h1_b, p_Dn,
                            p_u1, NN, p_st + 256, bn2_g, bn2_b, p_aff + 256, p_tick + 1);

    // ---- hgconv2 (H=1) ----
    k_rowvec_ae<1><<<NWB, 256>>>(p_u1, p_aff + 256, p_wx2, p_we2, p_noff, p_nedge,
                                 p_an2, p_ae2, NN);
    k_softmax_t<1><<<TNB, 256>>>(p_an2, p_ae2, p_noff, p_nedge, p_a2, NN);
    k_gather<1><<<MM, 128>>>(p_u1, p_aff + 256, p_a2, p_eoff, p_enode, p_eposn, p_g2);
    k_gemm2<false, false, false, false, false><<<dim3(GBM, 1), 256>>>(
        p_g2, nullptr, h2_w, 128, 128, 0, nullptr, nullptr, p_eo2, MM, nullptr,
        nullptr, nullptr, nullptr, nullptr);
    k_out<1><<<OUTB, 256>>>(p_eo2, p_a2, p_noff, p_nedge, p_u1, p_aff + 256, h2_b, p_Dn,
                            p_u2, NN, p_st + 512, bn3_g, bn3_b, p_aff + 512, p_tick + 2);

    // ---- final: wbuf = x + lrelu(affine3(u2)@lin2+b2); stats + BN4 finalize ----
    k_gemm2<true, true, true, true, true><<<dim3(GB2, 1), 256>>>(
        p_u2, p_aff + 512, lin2_w, 128, 128, 0, lin2_b, x, p_wbuf, NN, p_st + 768,
        bn4_g, bn4_b, p_aff + 768, p_tick + 3);
    k_final<<<(NN * 32 + 255) / 256, 256>>>((const float4*)p_wbuf, p_aff + 768,
                                            (float4*)out, NN * 32);
}